// round 6
// baseline (speedup 1.0000x reference)
#include <cuda_runtime.h>
#include <cuda_fp16.h>
#include <stdint.h>

#define SEQ   4096
#define TTOK  16384
#define HID   2048
#define CINC  4096
#define COUTC 4096
#define GCH   512

#define BM 128
#define BN 128
#define BK 64
#define NST 3
#define NTHR 512
#define STAGE_A (BM * BK * 2)                 // 16 KB
#define STAGE_BYTES (STAGE_A + BN * BK * 2)   // 32 KB
#define SMEM_TOTAL (NST * STAGE_BYTES)        // 96 KB -> 2 CTAs/SM

// fp16 copies of operands + intermediates (allocation-free rule: __device__ globals)
__device__ __half g_x16[(size_t)TTOK * HID];
__device__ __half g_h16[(size_t)TTOK * CINC];
__device__ __half g_y16[(size_t)TTOK * COUTC];
__device__ __half g_wi [(size_t)CINC * HID];
__device__ __half g_wo [(size_t)HID * COUTC];
__device__ __half g_w2 [(size_t)COUTC * 2048];

// One merged prep launch (4 regions)
#define P0 (TTOK * HID / 2)
#define P1 (P0 + CINC * HID / 2)
#define P2 (P1 + HID * COUTC / 2)
#define P3 (P2 + COUTC * 2048)
__global__ void prep_all_kernel(
    const float* __restrict__ x,  const float* __restrict__ wi_f,
    const float* __restrict__ wo_f, const float* __restrict__ cw,
    __half* __restrict__ x16, __half* __restrict__ wi,
    __half* __restrict__ wo,  __half* __restrict__ w2)
{
    int i = blockIdx.x * blockDim.x + threadIdx.x;
    if (i < P0) {
        float2 v = ((const float2*)x)[i];
        ((__half2*)x16)[i] = __floats2half2_rn(v.x, v.y);
    } else if (i < P1) {
        int j = i - P0;
        float2 v = ((const float2*)wi_f)[j];
        ((__half2*)wi)[j] = __floats2half2_rn(v.x, v.y);
    } else if (i < P2) {
        int j = i - P1;
        float2 v = ((const float2*)wo_f)[j];
        ((__half2*)wo)[j] = __floats2half2_rn(v.x, v.y);
    } else if (i < P3) {
        int j = i - P2;
        int co = j >> 11, r = j & 2047, tap = r >> 9, ci = r & 511;
        w2[j] = __float2half_rn(cw[(co * GCH + ci) * 4 + tap]);
    }
}

__device__ __forceinline__ uint32_t smem_u32(const void* p) {
    uint32_t a;
    asm("{ .reg .u64 t; cvta.to.shared.u64 t, %1; cvt.u32.u64 %0, t; }" : "=r"(a) : "l"(p));
    return a;
}

#define SW(x) ((x) ^ (((x) >> 3) & 0x70))

#define CPA(dst_, src_) \
    asm volatile("cp.async.cg.shared.global [%0], [%1], 16;" :: "r"(dst_), "l"(src_))
#define CPAZ(dst_, src_, sz_) \
    asm volatile("cp.async.cg.shared.global [%0], [%1], 16, %2;" :: "r"(dst_), "l"(src_), "r"(sz_))

#define LDSM4(r_, a_) \
    asm volatile("ldmatrix.sync.aligned.m8n8.x4.shared.b16 {%0,%1,%2,%3}, [%4];" \
        : "=r"((r_)[0]), "=r"((r_)[1]), "=r"((r_)[2]), "=r"((r_)[3]) : "r"(a_))

#define MMA16(c_, a_, b_) \
    asm volatile("mma.sync.aligned.m16n8k16.row.col.f32.f16.f16.f32 " \
        "{%0,%1,%2,%3},{%4,%5,%6,%7},{%8,%9},{%0,%1,%2,%3};" \
        : "+f"((c_)[0]), "+f"((c_)[1]), "+f"((c_)[2]), "+f"((c_)[3]) \
        : "r"((a_)[0]), "r"((a_)[1]), "r"((a_)[2]), "r"((a_)[3]), \
          "r"((b_)[0]), "r"((b_)[1]))

// Issue cp.async for one BK=64 K-tile into stage s_. 512 thr: 2 A + 2 B chunks.
#define ISSUE(kt_, s_) do {                                                         \
    const int k0_ = (kt_) * BK;                                                     \
    const uint32_t ab_ = sb + (s_) * STAGE_BYTES;                                   \
    const uint32_t bb_ = ab_ + STAGE_A;                                             \
    if (!CONV) {                                                                    \
        _Pragma("unroll")                                                           \
        for (int j = 0; j < 2; j++) {                                               \
            int id_ = tid + j * NTHR, row_ = id_ >> 3, c_ = id_ & 7;                \
            const __half* s_p = A + (size_t)(t0 + row_) * K + k0_ + c_ * 8;         \
            CPA(ab_ + SW(row_ * 128 + c_ * 16), s_p);                               \
        }                                                                           \
    } else {                                                                        \
        const int tap_ = k0_ >> 9;                                                  \
        const int cb_  = grp * GCH + (k0_ & 511);                                   \
        _Pragma("unroll")                                                           \
        for (int j = 0; j < 2; j++) {                                               \
            int id_ = tid + j * NTHR, row_ = id_ >> 3, c_ = id_ & 7;                \
            int tk_ = t0 + row_;                                                    \
            uint32_t ok_ = (((tk_ & (SEQ - 1)) + tap_) >= 3) ? 16u : 0u;            \
            const __half* s_p = ok_                                                 \
                ? A + (size_t)(tk_ + tap_ - 3) * CINC + cb_ + c_ * 8 : A;           \
            CPAZ(ab_ + SW(row_ * 128 + c_ * 16), s_p, ok_);                         \
        }                                                                           \
    }                                                                               \
    _Pragma("unroll")                                                               \
    for (int j = 0; j < 2; j++) {                                                   \
        int id_ = tid + j * NTHR, row_ = id_ >> 3, c_ = id_ & 7;                    \
        const __half* s_p = Bw + (size_t)(n0 + row_) * K + k0_ + c_ * 8;            \
        CPA(bb_ + SW(row_ * 128 + c_ * 16), s_p);                                   \
    }                                                                               \
} while (0)

// C[t,n] = act( sum_j A'[t,j] * Bw[n,j] + bias[n] )
// 16 warps (4x4), warp tile 32x32, 2 CTA/SM target (64-reg budget)
template<bool CONV, bool SILU, bool OUTF32>
__global__ void __launch_bounds__(NTHR, 2) gemm_h(
    const __half* __restrict__ A, const __half* __restrict__ Bw,
    const float* __restrict__ bias, void* __restrict__ Cp,
    int K, int Nt)
{
    extern __shared__ char smem[];
    const uint32_t sb = smem_u32(smem);
    const int tid = threadIdx.x, lane = tid & 31, warp = tid >> 5;
    const int wm = (warp & 3) * 32, wn = (warp >> 2) * 32;
    const int t0 = blockIdx.x * BM, n0 = blockIdx.y * BN;
    const int grp = n0 >> 9;

    float acc[2][4][4];
#pragma unroll
    for (int a = 0; a < 2; a++)
#pragma unroll
        for (int b = 0; b < 4; b++)
#pragma unroll
            for (int c = 0; c < 4; c++) acc[a][b][c] = 0.f;

    const int nK = K / BK;

    for (int p = 0; p < NST - 1; p++) {
        ISSUE(p, p);
        asm volatile("cp.async.commit_group;" ::: "memory");
    }

    const int mtx  = lane >> 3;
    const int arow = (mtx & 1) * 8 + (lane & 7);
    const int acol = mtx >> 1;
    const int brow = (mtx >> 1) * 8 + (lane & 7);
    const int bcol = mtx & 1;

    for (int kt = 0; kt < nK; kt++) {
        asm volatile("cp.async.wait_group %0;" :: "n"(NST - 2) : "memory");
        __syncthreads();
        if (kt + NST - 1 < nK) ISSUE(kt + NST - 1, (kt + NST - 1) % NST);
        asm volatile("cp.async.commit_group;" ::: "memory");

        const uint32_t ab = sb + (kt % NST) * STAGE_BYTES;
        const uint32_t bb = ab + STAGE_A;
#pragma unroll
        for (int ks = 0; ks < 4; ks++) {
            uint32_t af[2][4], bq[2][4];
#pragma unroll
            for (int mf = 0; mf < 2; mf++) {
                int row = wm + mf * 16 + arow;
                LDSM4(af[mf], ab + SW(row * 128 + (2 * ks + acol) * 16));
            }
#pragma unroll
            for (int pr = 0; pr < 2; pr++) {
                int row = wn + pr * 16 + brow;
                LDSM4(bq[pr], bb + SW(row * 128 + (2 * ks + bcol) * 16));
            }
#pragma unroll
            for (int mf = 0; mf < 2; mf++)
#pragma unroll
                for (int nf = 0; nf < 4; nf++)
                    MMA16(acc[mf][nf], af[mf], &bq[nf >> 1][(nf & 1) * 2]);
        }
    }

    // Epilogue: bias (+ SiLU); fp16 out for intermediates, fp32 for final
#pragma unroll
    for (int mf = 0; mf < 2; mf++) {
        int r = t0 + wm + mf * 16 + (lane >> 2);
#pragma unroll
        for (int nf = 0; nf < 4; nf++) {
            int cc = n0 + wn + nf * 8 + (lane & 3) * 2;
            float b0v = __ldg(bias + cc), b1v = __ldg(bias + cc + 1);
            float v0 = acc[mf][nf][0] + b0v;
            float v1 = acc[mf][nf][1] + b1v;
            float v2 = acc[mf][nf][2] + b0v;
            float v3 = acc[mf][nf][3] + b1v;
            if (SILU) {
                v0 *= 1.f / (1.f + __expf(-v0));
                v1 *= 1.f / (1.f + __expf(-v1));
                v2 *= 1.f / (1.f + __expf(-v2));
                v3 *= 1.f / (1.f + __expf(-v3));
            }
            if (OUTF32) {
                float* C = (float*)Cp;
                *(float2*)(C + (size_t)r * Nt + cc)       = make_float2(v0, v1);
                *(float2*)(C + (size_t)(r + 8) * Nt + cc) = make_float2(v2, v3);
            } else {
                __half2* C = (__half2*)Cp;
                C[((size_t)r * Nt + cc) >> 1]       = __floats2half2_rn(v0, v1);
                C[((size_t)(r + 8) * Nt + cc) >> 1] = __floats2half2_rn(v2, v3);
            }
        }
    }
}

extern "C" void kernel_launch(void* const* d_in, const int* in_sizes, int n_in,
                              void* d_out, int out_size)
{
    const float* x      = (const float*)d_in[0];
    const float* W_in   = (const float*)d_in[1];
    const float* b_in   = (const float*)d_in[2];
    const float* conv_w = (const float*)d_in[3];
    const float* conv_b = (const float*)d_in[4];
    const float* W_out  = (const float*)d_in[5];
    const float* b_out  = (const float*)d_in[6];
    float* out = (float*)d_out;

    __half *x16, *h16, *y16, *wi, *wo, *w2;
    cudaGetSymbolAddress((void**)&x16, g_x16);
    cudaGetSymbolAddress((void**)&h16, g_h16);
    cudaGetSymbolAddress((void**)&y16, g_y16);
    cudaGetSymbolAddress((void**)&wi,  g_wi);
    cudaGetSymbolAddress((void**)&wo,  g_wo);
    cudaGetSymbolAddress((void**)&w2,  g_w2);

    cudaFuncSetAttribute(gemm_h<false, false, false>,
                         cudaFuncAttributeMaxDynamicSharedMemorySize, SMEM_TOTAL);
    cudaFuncSetAttribute(gemm_h<true, true, false>,
                         cudaFuncAttributeMaxDynamicSharedMemorySize, SMEM_TOTAL);
    cudaFuncSetAttribute(gemm_h<false, false, true>,
                         cudaFuncAttributeMaxDynamicSharedMemorySize, SMEM_TOTAL);

    prep_all_kernel<<<(P3 + 255) / 256, 256>>>(x, W_in, W_out, conv_w,
                                               x16, wi, wo, w2);

    // Stage 1: h = x @ W_in^T + b_in               (K=2048, N=4096) -> fp16
    gemm_h<false, false, false><<<dim3(TTOK / BM, CINC / BN), NTHR, SMEM_TOTAL>>>(
        x16, wi, b_in, h16, HID, CINC);
    // Stage 2: y = silu(im2col(h) @ w2^T + conv_b) (K=2048, N=4096) -> fp16
    gemm_h<true, true, false><<<dim3(TTOK / BM, COUTC / BN), NTHR, SMEM_TOTAL>>>(
        h16, w2, conv_b, y16, 2048, COUTC);
    // Stage 3: out = y @ W_out^T + b_out           (K=4096, N=2048) -> fp32
    gemm_h<false, false, true><<<dim3(TTOK / BM, HID / BN), NTHR, SMEM_TOTAL>>>(
        y16, wo, b_out, out, COUTC, HID);
}

// round 8
// speedup vs baseline: 1.1306x; 1.1306x over previous
#include <cuda_runtime.h>
#include <cuda_fp16.h>
#include <stdint.h>

#define SEQ   4096
#define TTOK  16384
#define HID   2048
#define CINC  4096
#define COUTC 4096
#define GCH   512

#define BM 128
#define BN 128
#define BK 64
#define NST 3
#define NTHR 128
#define STAGE_A (BM * BK * 2)                 // 16 KB
#define STAGE_BYTES (STAGE_A + BN * BK * 2)   // 32 KB
#define SMEM_TOTAL (NST * STAGE_BYTES)        // 96 KB -> 2 CTAs/SM

// fp16 copies of operands + intermediates (allocation-free rule: __device__ globals)
__device__ __half g_x16[(size_t)TTOK * HID];
__device__ __half g_h16[(size_t)TTOK * CINC];
__device__ __half g_y16[(size_t)TTOK * COUTC];
__device__ __half g_wi [(size_t)CINC * HID];
__device__ __half g_wo [(size_t)HID * COUTC];
__device__ __half g_w2 [(size_t)COUTC * 2048];

// One merged prep launch (4 regions)
#define P0 (TTOK * HID / 2)
#define P1 (P0 + CINC * HID / 2)
#define P2 (P1 + HID * COUTC / 2)
#define P3 (P2 + COUTC * 2048)
__global__ void prep_all_kernel(
    const float* __restrict__ x,  const float* __restrict__ wi_f,
    const float* __restrict__ wo_f, const float* __restrict__ cw,
    __half* __restrict__ x16, __half* __restrict__ wi,
    __half* __restrict__ wo,  __half* __restrict__ w2)
{
    int i = blockIdx.x * blockDim.x + threadIdx.x;
    if (i < P0) {
        float2 v = ((const float2*)x)[i];
        ((__half2*)x16)[i] = __floats2half2_rn(v.x, v.y);
    } else if (i < P1) {
        int j = i - P0;
        float2 v = ((const float2*)wi_f)[j];
        ((__half2*)wi)[j] = __floats2half2_rn(v.x, v.y);
    } else if (i < P2) {
        int j = i - P1;
        float2 v = ((const float2*)wo_f)[j];
        ((__half2*)wo)[j] = __floats2half2_rn(v.x, v.y);
    } else if (i < P3) {
        int j = i - P2;
        int co = j >> 11, r = j & 2047, tap = r >> 9, ci = r & 511;
        w2[j] = __float2half_rn(cw[(co * GCH + ci) * 4 + tap]);
    }
}

__device__ __forceinline__ uint32_t smem_u32(const void* p) {
    uint32_t a;
    asm("{ .reg .u64 t; cvta.to.shared.u64 t, %1; cvt.u32.u64 %0, t; }" : "=r"(a) : "l"(p));
    return a;
}

#define SW(x) ((x) ^ (((x) >> 3) & 0x70))

#define CPA(dst_, src_) \
    asm volatile("cp.async.cg.shared.global [%0], [%1], 16;" :: "r"(dst_), "l"(src_))
#define CPAZ(dst_, src_, sz_) \
    asm volatile("cp.async.cg.shared.global [%0], [%1], 16, %2;" :: "r"(dst_), "l"(src_), "r"(sz_))

#define LDSM4(r_, a_) \
    asm volatile("ldmatrix.sync.aligned.m8n8.x4.shared.b16 {%0,%1,%2,%3}, [%4];" \
        : "=r"((r_)[0]), "=r"((r_)[1]), "=r"((r_)[2]), "=r"((r_)[3]) : "r"(a_))

#define MMA16(c_, a_, b_) \
    asm volatile("mma.sync.aligned.m16n8k16.row.col.f32.f16.f16.f32 " \
        "{%0,%1,%2,%3},{%4,%5,%6,%7},{%8,%9},{%0,%1,%2,%3};" \
        : "+f"((c_)[0]), "+f"((c_)[1]), "+f"((c_)[2]), "+f"((c_)[3]) \
        : "r"((a_)[0]), "r"((a_)[1]), "r"((a_)[2]), "r"((a_)[3]), \
          "r"((b_)[0]), "r"((b_)[1]))

// Issue cp.async for one BK=64 K-tile into stage s_. 128 thr: 8 A + 8 B chunks.
#define ISSUE(kt_, s_) do {                                                         \
    const int k0_ = (kt_) * BK;                                                     \
    const uint32_t ab_ = sb + (s_) * STAGE_BYTES;                                   \
    const uint32_t bb_ = ab_ + STAGE_A;                                             \
    if (!CONV) {                                                                    \
        _Pragma("unroll")                                                           \
        for (int j = 0; j < 8; j++) {                                               \
            int id_ = tid + j * NTHR, row_ = id_ >> 3, c_ = id_ & 7;                \
            const __half* s_p = A + (size_t)(t0 + row_) * K + k0_ + c_ * 8;         \
            CPA(ab_ + SW(row_ * 128 + c_ * 16), s_p);                               \
        }                                                                           \
    } else {                                                                        \
        const int tap_ = k0_ >> 9;                                                  \
        const int cb_  = grp * GCH + (k0_ & 511);                                   \
        _Pragma("unroll")                                                           \
        for (int j = 0; j < 8; j++) {                                               \
            int id_ = tid + j * NTHR, row_ = id_ >> 3, c_ = id_ & 7;                \
            int tk_ = t0 + row_;                                                    \
            uint32_t ok_ = (((tk_ & (SEQ - 1)) + tap_) >= 3) ? 16u : 0u;            \
            const __half* s_p = ok_                                                 \
                ? A + (size_t)(tk_ + tap_ - 3) * CINC + cb_ + c_ * 8 : A;           \
            CPAZ(ab_ + SW(row_ * 128 + c_ * 16), s_p, ok_);                         \
        }                                                                           \
    }                                                                               \
    _Pragma("unroll")                                                               \
    for (int j = 0; j < 8; j++) {                                                   \
        int id_ = tid + j * NTHR, row_ = id_ >> 3, c_ = id_ & 7;                    \
        const __half* s_p = Bw + (size_t)(n0 + row_) * K + k0_ + c_ * 8;            \
        CPA(bb_ + SW(row_ * 128 + c_ * 16), s_p);                                   \
    }                                                                               \
} while (0)

// C[t,n] = act( sum_j A'[t,j] * Bw[n,j] + bias[n] )
// 4 warps (2x2), warp tile 64x64 (min crossbar B/MMA), 2 CTAs/SM
template<bool CONV, bool SILU, bool OUTF32>
__global__ void __launch_bounds__(NTHR, 2) gemm_h(
    const __half* __restrict__ A, const __half* __restrict__ Bw,
    const float* __restrict__ bias, void* __restrict__ Cp,
    int K, int Nt)
{
    extern __shared__ char smem[];
    const uint32_t sb = smem_u32(smem);
    const int tid = threadIdx.x, lane = tid & 31, warp = tid >> 5;
    const int wm = (warp & 1) * 64, wn = (warp >> 1) * 64;
    const int t0 = blockIdx.x * BM, n0 = blockIdx.y * BN;
    const int grp = n0 >> 9;

    float acc[4][8][4];
#pragma unroll
    for (int a = 0; a < 4; a++)
#pragma unroll
        for (int b = 0; b < 8; b++)
#pragma unroll
            for (int c = 0; c < 4; c++) acc[a][b][c] = 0.f;

    const int nK = K / BK;

    for (int p = 0; p < NST - 1; p++) {
        ISSUE(p, p);
        asm volatile("cp.async.commit_group;" ::: "memory");
    }

    const int mtx  = lane >> 3;
    const int arow = (mtx & 1) * 8 + (lane & 7);
    const int acol = mtx >> 1;
    const int brow = (mtx >> 1) * 8 + (lane & 7);
    const int bcol = mtx & 1;

    for (int kt = 0; kt < nK; kt++) {
        asm volatile("cp.async.wait_group %0;" :: "n"(NST - 2) : "memory");
        __syncthreads();
        if (kt + NST - 1 < nK) ISSUE(kt + NST - 1, (kt + NST - 1) % NST);
        asm volatile("cp.async.commit_group;" ::: "memory");

        const uint32_t ab = sb + (kt % NST) * STAGE_BYTES;
        const uint32_t bb = ab + STAGE_A;
#pragma unroll
        for (int ks = 0; ks < 4; ks++) {
            uint32_t af[4][4], bq[4][4];
#pragma unroll
            for (int mf = 0; mf < 4; mf++) {
                int row = wm + mf * 16 + arow;
                LDSM4(af[mf], ab + SW(row * 128 + (2 * ks + acol) * 16));
            }
#pragma unroll
            for (int pr = 0; pr < 4; pr++) {
                int row = wn + pr * 16 + brow;
                LDSM4(bq[pr], bb + SW(row * 128 + (2 * ks + bcol) * 16));
            }
#pragma unroll
            for (int mf = 0; mf < 4; mf++)
#pragma unroll
                for (int nf = 0; nf < 8; nf++)
                    MMA16(acc[mf][nf], af[mf], &bq[nf >> 1][(nf & 1) * 2]);
        }
    }

    // Epilogue: bias (+ SiLU); fp16 out for intermediates, fp32 for final
#pragma unroll
    for (int mf = 0; mf < 4; mf++) {
        int r = t0 + wm + mf * 16 + (lane >> 2);
#pragma unroll
        for (int nf = 0; nf < 8; nf++) {
            int cc = n0 + wn + nf * 8 + (lane & 3) * 2;
            float b0v = __ldg(bias + cc), b1v = __ldg(bias + cc + 1);
            float v0 = acc[mf][nf][0] + b0v;
            float v1 = acc[mf][nf][1] + b1v;
            float v2 = acc[mf][nf][2] + b0v;
            float v3 = acc[mf][nf][3] + b1v;
            if (SILU) {
                v0 *= 1.f / (1.f + __expf(-v0));
                v1 *= 1.f / (1.f + __expf(-v1));
                v2 *= 1.f / (1.f + __expf(-v2));
                v3 *= 1.f / (1.f + __expf(-v3));
            }
            if (OUTF32) {
                float* C = (float*)Cp;
                *(float2*)(C + (size_t)r * Nt + cc)       = make_float2(v0, v1);
                *(float2*)(C + (size_t)(r + 8) * Nt + cc) = make_float2(v2, v3);
            } else {
                __half2* C = (__half2*)Cp;
                C[((size_t)r * Nt + cc) >> 1]       = __floats2half2_rn(v0, v1);
                C[((size_t)(r + 8) * Nt + cc) >> 1] = __floats2half2_rn(v2, v3);
            }
        }
    }
}

extern "C" void kernel_launch(void* const* d_in, const int* in_sizes, int n_in,
                              void* d_out, int out_size)
{
    const float* x      = (const float*)d_in[0];
    const float* W_in   = (const float*)d_in[1];
    const float* b_in   = (const float*)d_in[2];
    const float* conv_w = (const float*)d_in[3];
    const float* conv_b = (const float*)d_in[4];
    const float* W_out  = (const float*)d_in[5];
    const float* b_out  = (const float*)d_in[6];
    float* out = (float*)d_out;

    __half *x16, *h16, *y16, *wi, *wo, *w2;
    cudaGetSymbolAddress((void**)&x16, g_x16);
    cudaGetSymbolAddress((void**)&h16, g_h16);
    cudaGetSymbolAddress((void**)&y16, g_y16);
    cudaGetSymbolAddress((void**)&wi,  g_wi);
    cudaGetSymbolAddress((void**)&wo,  g_wo);
    cudaGetSymbolAddress((void**)&w2,  g_w2);

    cudaFuncSetAttribute(gemm_h<false, false, false>,
                         cudaFuncAttributeMaxDynamicSharedMemorySize, SMEM_TOTAL);
    cudaFuncSetAttribute(gemm_h<true, true, false>,
                         cudaFuncAttributeMaxDynamicSharedMemorySize, SMEM_TOTAL);
    cudaFuncSetAttribute(gemm_h<false, false, true>,
                         cudaFuncAttributeMaxDynamicSharedMemorySize, SMEM_TOTAL);

    prep_all_kernel<<<(P3 + 255) / 256, 256>>>(x, W_in, W_out, conv_w,
                                               x16, wi, wo, w2);

    // Stage 1: h = x @ W_in^T + b_in               (K=2048, N=4096) -> fp16
    gemm_h<false, false, false><<<dim3(TTOK / BM, CINC / BN), NTHR, SMEM_TOTAL>>>(
        x16, wi, b_in, h16, HID, CINC);
    // Stage 2: y = silu(im2col(h) @ w2^T + conv_b) (K=2048, N=4096) -> fp16
    gemm_h<true, true, false><<<dim3(TTOK / BM, COUTC / BN), NTHR, SMEM_TOTAL>>>(
        h16, w2, conv_b, y16, 2048, COUTC);
    // Stage 3: out = y @ W_out^T + b_out           (K=4096, N=2048) -> fp32
    gemm_h<false, false, true><<<dim3(TTOK / BM, HID / BN), NTHR, SMEM_TOTAL>>>(
        y16, wo, b_out, out, COUTC, HID);
}